// round 7
// baseline (speedup 1.0000x reference)
#include <cuda_runtime.h>
#include <cuda_bf16.h>
#include <float.h>
#include <stdint.h>

#define D_DIM   64
#define K_CODES 512
#define BLOCK   512          // 16 warps: 8 row-groups x 2 n-halves
#define GRID    148
#define NROWS   65536
#define NTILES  512          // 128 rows per tile

// ---- SMEM layout (bytes) ----
// B fragments in mma-fragment order, idx = ((nt*4+ks)*32 + lane):
//   sHM: uint4 {bh0, bh1, bm0, bm1}   (8192 * 16B = 128KB)
//   sL : uint2 {bl0, bl1}             (8192 *  8B =  64KB)
#define SM_HM 0
#define SM_L  131072
#define SM_SN 196608         // 512 floats  (code norms)
#define SM_BD 198656         // 256 floats  (per-half best dist)
#define SM_BI 199680         // 256 ints    (per-half best idx)
#define SM_XN 200704         // 128 floats  (row norms)
#define SM_BK 201216         // 128 ints    (merged best idx)
#define SM_LS 201728         // 16 doubles
#define SMEM_TOTAL 201856

__device__ float        g_embT[K_CODES * D_DIM];   // exact fp32 codebook [k][d]
__device__ double       g_partial[GRID];
__device__ unsigned int g_cnt = 0;

#define MMA(acc, a, b0, b1)                                                     \
    asm volatile(                                                               \
        "mma.sync.aligned.m16n8k16.row.col.f32.bf16.bf16.f32 "                  \
        "{%0,%1,%2,%3}, {%4,%5,%6,%7}, {%8,%9}, {%0,%1,%2,%3};"                 \
        : "+f"((acc)[0]), "+f"((acc)[1]), "+f"((acc)[2]), "+f"((acc)[3])        \
        : "r"((a)[0]), "r"((a)[1]), "r"((a)[2]), "r"((a)[3]), "r"(b0), "r"(b1))

__device__ __forceinline__ uint32_t pack_bf2(__nv_bfloat16 lo, __nv_bfloat16 hi) {
    return (uint32_t)__bfloat16_as_ushort(lo) | ((uint32_t)__bfloat16_as_ushort(hi) << 16);
}

// 3-way exact-residual bf16 split of a float pair
__device__ __forceinline__ void split3(float a, float b,
                                       uint32_t& ph, uint32_t& pm, uint32_t& pl) {
    __nv_bfloat16 ha = __float2bfloat16(a), hb = __float2bfloat16(b);
    float ra = a - __bfloat162float(ha), rb = b - __bfloat162float(hb);
    __nv_bfloat16 ma = __float2bfloat16(ra), mb = __float2bfloat16(rb);
    float r2a = ra - __bfloat162float(ma), r2b = rb - __bfloat162float(mb);
    __nv_bfloat16 la = __float2bfloat16(r2a), lb = __float2bfloat16(r2b);
    ph = pack_bf2(ha, hb); pm = pack_bf2(ma, mb); pl = pack_bf2(la, lb);
}

__device__ __forceinline__ void upd(float& b, int& bi, float d, int idx) {
    if (d < b) { b = d; bi = idx; }
}

__global__ void __launch_bounds__(BLOCK, 1)
vq_mma(const float* __restrict__ x, const float* __restrict__ emb,
       float* __restrict__ out, int write_loss)
{
    extern __shared__ char smem[];
    uint4*  sHM = (uint4*)(smem + SM_HM);
    uint2*  sL  = (uint2*)(smem + SM_L);
    float*  snm = (float*)(smem + SM_SN);
    float*  sbd = (float*)(smem + SM_BD);
    int*    sbi = (int*)(smem + SM_BI);
    float*  sxn = (float*)(smem + SM_XN);
    int*    sbk = (int*)(smem + SM_BK);
    double* sls = (double*)(smem + SM_LS);

    const int tid  = threadIdx.x;
    const int w    = tid >> 5;
    const int lane = tid & 31;
    const int g    = lane >> 2;
    const int c    = lane & 3;
    const int rg   = w & 7;      // row-group: 16 rows each
    const int nh   = w >> 3;     // n-half: codes [nh*256, nh*256+256)

    // ---- Prologue: B fragments (3-way bf16 split) + exact fp32 transpose ----
    for (int i = tid; i < 8192; i += BLOCK) {
        int nt = i >> 7;
        int ks = (i >> 5) & 3;
        int ln = i & 31;
        int fg = ln >> 2, fc = ln & 3;
        int n  = nt * 8 + fg;
        int d0 = ks * 16 + fc * 2;
        float e00 = __ldg(emb + (d0 + 0) * K_CODES + n);
        float e01 = __ldg(emb + (d0 + 1) * K_CODES + n);
        float e10 = __ldg(emb + (d0 + 8) * K_CODES + n);
        float e11 = __ldg(emb + (d0 + 9) * K_CODES + n);
        uint32_t bh0, bm0, bl0, bh1, bm1, bl1;
        split3(e00, e01, bh0, bm0, bl0);
        split3(e10, e11, bh1, bm1, bl1);
        sHM[i] = make_uint4(bh0, bh1, bm0, bm1);
        sL[i]  = make_uint2(bl0, bl1);
        g_embT[n * D_DIM + d0]     = e00;
        g_embT[n * D_DIM + d0 + 1] = e01;
        g_embT[n * D_DIM + d0 + 8] = e10;
        g_embT[n * D_DIM + d0 + 9] = e11;
    }
    for (int k = tid; k < K_CODES; k += BLOCK) {
        float s = 0.f;
        #pragma unroll 8
        for (int d = 0; d < D_DIM; d++) { float v = emb[d * K_CODES + k]; s = fmaf(v, v, s); }
        snm[k] = s;
    }
    __syncthreads();

    double lacc = 0.0;

    for (int tile = blockIdx.x; tile < NTILES; tile += GRID) {
        const int rbase = tile * 128 + rg * 16 + g;

        // ---- A fragments: rows rbase, rbase+8; 3 splits, 4 k-steps ----
        uint32_t Ah[4][4], Am[4][4], Al[4][4];
        float xn0 = 0.f, xn1 = 0.f;
        {
            const float* xr0 = x + (size_t)rbase * D_DIM;
            const float* xr1 = xr0 + 8 * D_DIM;
            #pragma unroll
            for (int ks = 0; ks < 4; ks++) {
                #pragma unroll
                for (int p = 0; p < 2; p++) {
                    int col = 2 * c + 8 * p + 16 * ks;
                    float2 v0 = *(const float2*)(xr0 + col);
                    float2 v1 = *(const float2*)(xr1 + col);
                    xn0 = fmaf(v0.x, v0.x, fmaf(v0.y, v0.y, xn0));
                    xn1 = fmaf(v1.x, v1.x, fmaf(v1.y, v1.y, xn1));
                    split3(v0.x, v0.y, Ah[ks][2*p],   Am[ks][2*p],   Al[ks][2*p]);
                    split3(v1.x, v1.y, Ah[ks][2*p+1], Am[ks][2*p+1], Al[ks][2*p+1]);
                }
            }
        }

        float best0 = FLT_MAX, best1 = FLT_MAX;
        int   bi0 = 0, bi1 = 0;

        // ---- main loop: 32 n-tiles for this half, 4 at a time, 2 accs each ----
        const int ntbeg = nh * 32;
        #pragma unroll 1
        for (int nt0 = ntbeg; nt0 < ntbeg + 32; nt0 += 4) {
            float accA[4][4], accB[4][4];
            #pragma unroll
            for (int u = 0; u < 4; u++)
                #pragma unroll
                for (int r = 0; r < 4; r++) { accA[u][r] = 0.f; accB[u][r] = 0.f; }

            #pragma unroll
            for (int ks = 0; ks < 4; ks++) {
                #pragma unroll
                for (int u = 0; u < 4; u++) {
                    const int idx = ((nt0 + u) * 4 + ks) * 32 + lane;
                    uint4 hm = sHM[idx];      // {bh0, bh1, bm0, bm1}
                    uint2 lo = sL[idx];       // {bl0, bl1}
                    MMA(accA[u], Ah[ks], hm.x, hm.y);   // hh
                    MMA(accB[u], Am[ks], hm.x, hm.y);   // mh
                    MMA(accA[u], Al[ks], hm.x, hm.y);   // lh
                    MMA(accB[u], Ah[ks], hm.z, hm.w);   // hm
                    MMA(accA[u], Am[ks], hm.z, hm.w);   // mm
                    MMA(accB[u], Ah[ks], lo.x, lo.y);   // hl
                }
            }

            #pragma unroll
            for (int u = 0; u < 4; u++) {
                const int kb = (nt0 + u) * 8 + 2 * c;
                float2 s2 = *(const float2*)(snm + kb);
                float d00 = accA[u][0] + accB[u][0];
                float d01 = accA[u][1] + accB[u][1];
                float d10 = accA[u][2] + accB[u][2];
                float d11 = accA[u][3] + accB[u][3];
                upd(best0, bi0, fmaf(-2.f, d00, s2.x), kb);
                upd(best0, bi0, fmaf(-2.f, d01, s2.y), kb + 1);
                upd(best1, bi1, fmaf(-2.f, d10, s2.x), kb);
                upd(best1, bi1, fmaf(-2.f, d11, s2.y), kb + 1);
            }
        }

        // ---- quad reduce across c (lanes xor 1,2 share rows) ----
        #pragma unroll
        for (int off = 1; off <= 2; off <<= 1) {
            float ob; int oi; float ox;
            ob = __shfl_xor_sync(0xffffffffu, best0, off);
            oi = __shfl_xor_sync(0xffffffffu, bi0,   off);
            if (ob < best0 || (ob == best0 && oi < bi0)) { best0 = ob; bi0 = oi; }
            ob = __shfl_xor_sync(0xffffffffu, best1, off);
            oi = __shfl_xor_sync(0xffffffffu, bi1,   off);
            if (ob < best1 || (ob == best1 && oi < bi1)) { best1 = ob; bi1 = oi; }
            ox = __shfl_xor_sync(0xffffffffu, xn0, off); xn0 += ox;
            ox = __shfl_xor_sync(0xffffffffu, xn1, off); xn1 += ox;
        }

        if (c == 0) {
            const int r = rg * 16 + g;           // row within tile
            sbd[nh * 128 + r]     = best0;
            sbi[nh * 128 + r]     = bi0;
            sbd[nh * 128 + r + 8] = best1;
            sbi[nh * 128 + r + 8] = bi1;
            if (nh == 0) { sxn[r] = xn0; sxn[r + 8] = xn1; }
        }
        __syncthreads();

        // ---- merge halves (threads 0..127), accumulate loss ----
        if (tid < 128) {
            float d0 = sbd[tid]; int k0 = sbi[tid];
            float d1 = sbd[128 + tid];
            if (d1 < d0) { d0 = d1; k0 = sbi[128 + tid]; }   // nh=1 idx always larger
            sbk[tid] = k0;
            lacc += (double)(sxn[tid] + d0);
        }
        __syncthreads();

        // ---- output: exact fp32 codebook rows (4 threads per row) ----
        {
            const int r = tid >> 2;              // 0..127
            const int q = tid & 3;
            const int k = sbk[r];
            const float4* src = (const float4*)(g_embT + k * D_DIM) + q * 4;
            float4* dst = (float4*)(out + (size_t)(tile * 128 + r) * D_DIM) + q * 4;
            dst[0] = src[0]; dst[1] = src[1]; dst[2] = src[2]; dst[3] = src[3];
        }
        __syncthreads();   // sbk/sbd reused next tile
    }

    // ---- loss: warp reduce -> CTA partial -> last block finalizes ----
    #pragma unroll
    for (int off = 16; off > 0; off >>= 1)
        lacc += __shfl_down_sync(0xffffffffu, lacc, off);
    if (lane == 0) sls[w] = lacc;
    __syncthreads();
    if (tid == 0) {
        double t = 0.0;
        #pragma unroll
        for (int i = 0; i < 16; i++) t += sls[i];
        g_partial[blockIdx.x] = t;
        __threadfence();
        unsigned n = atomicAdd(&g_cnt, 1u);
        if (n == GRID - 1) {
            __threadfence();
            double tot = 0.0;
            for (int i = 0; i < GRID; i++) tot += g_partial[i];
            if (write_loss)
                out[(size_t)NROWS * D_DIM] =
                    (float)(tot * (1.25 / ((double)NROWS * (double)D_DIM)));
            g_cnt = 0;   // reset for next graph replay
        }
    }
}

extern "C" void kernel_launch(void* const* d_in, const int* in_sizes, int n_in,
                              void* d_out, int out_size)
{
    const float* x   = (const float*)d_in[0];
    const float* emb = (const float*)d_in[1];
    float* out = (float*)d_out;

    const int write_loss = (out_size > NROWS * D_DIM) ? 1 : 0;

    static int configured = 0;
    if (!configured) {
        cudaFuncSetAttribute(vq_mma, cudaFuncAttributeMaxDynamicSharedMemorySize, SMEM_TOTAL);
        configured = 1;
    }
    vq_mma<<<GRID, BLOCK, SMEM_TOTAL>>>(x, emb, out, write_loss);
}

// round 8
// speedup vs baseline: 1.1052x; 1.1052x over previous
#include <cuda_runtime.h>
#include <cuda_bf16.h>
#include <cuda_fp16.h>
#include <float.h>
#include <stdint.h>

#define D_DIM   64
#define K_CODES 512
#define BLOCK   512          // 16 warps: 8 row-groups x 2 n-halves
#define GRID    148
#define NROWS   65536
#define NTILES  512          // 128 rows per tile

// ---- SMEM layout (bytes) ----
#define SM_BH   0             // 8192 uint2 hi-bf16 B fragments (64KB)
#define SM_EST  65536         // est matrix: 128 rows x 520 halves (133120B)
#define EST_STRIDE 520        // halves per row (8 pad halves -> conflict-free)
#define SM_SN   198656        // 512 floats: exact ||e_k||^2
#define SM_SMIN 200704        // 256 floats: per-half row min est
#define SM_SXN  201728        // 128 floats: ||x_r||^2
#define SM_SRX  202240        // 128 floats: ||x_r - xh_r||^2
#define SM_THR  202752        // 128 floats: per-row candidate threshold
#define SM_BK   203264        // 128 ints: final argmin
#define SM_SE2  203776        // int: max_k ||e-eh||^2 (bits)
#define SM_SH2  203780        // int: max_k ||eh||^2 (bits)
#define SM_LS   203784        // 16 doubles
#define SMEM_TOTAL 203912

__device__ float        g_embT[K_CODES * D_DIM];   // exact fp32 codebook [k][d]
__device__ double       g_partial[GRID];
__device__ unsigned int g_cnt = 0;

#define MMA(acc, a, b0, b1)                                                     \
    asm volatile(                                                               \
        "mma.sync.aligned.m16n8k16.row.col.f32.bf16.bf16.f32 "                  \
        "{%0,%1,%2,%3}, {%4,%5,%6,%7}, {%8,%9}, {%0,%1,%2,%3};"                 \
        : "+f"((acc)[0]), "+f"((acc)[1]), "+f"((acc)[2]), "+f"((acc)[3])        \
        : "r"((a)[0]), "r"((a)[1]), "r"((a)[2]), "r"((a)[3]), "r"(b0), "r"(b1))

__device__ __forceinline__ uint32_t pack_bf2(float a, float b) {
    return (uint32_t)__bfloat16_as_ushort(__float2bfloat16(a))
         | ((uint32_t)__bfloat16_as_ushort(__float2bfloat16(b)) << 16);
}

__global__ void __launch_bounds__(BLOCK, 1)
vq_2stage(const float* __restrict__ x, const float* __restrict__ emb,
          float* __restrict__ out, int write_loss)
{
    extern __shared__ char smem[];
    uint2*   sBH  = (uint2*)(smem + SM_BH);
    __half*  sEst = (__half*)(smem + SM_EST);
    float*   snm  = (float*)(smem + SM_SN);
    float*   smin = (float*)(smem + SM_SMIN);
    float*   sxn  = (float*)(smem + SM_SXN);
    float*   srx  = (float*)(smem + SM_SRX);
    float*   sthr = (float*)(smem + SM_THR);
    int*     sbk  = (int*)(smem + SM_BK);
    int*     sSE2 = (int*)(smem + SM_SE2);
    int*     sSH2 = (int*)(smem + SM_SH2);
    double*  sls  = (double*)(smem + SM_LS);

    const int tid  = threadIdx.x;
    const int w    = tid >> 5;
    const int lane = tid & 31;
    const int g    = lane >> 2;
    const int c    = lane & 3;
    const int rg   = w & 7;      // row-group (16 rows)
    const int nh   = w >> 3;     // n-half: codes [nh*256, +256)

    if (tid < 2) { sSE2[0] = 0; sSH2[0] = 0; }
    __syncthreads();

    // ---- Prologue 1: hi-bf16 B fragments + exact fp32 transpose ----
    for (int i = tid; i < 8192; i += BLOCK) {
        int nt = i >> 7;
        int ks = (i >> 5) & 3;
        int ln = i & 31;
        int fg = ln >> 2, fc = ln & 3;
        int n  = nt * 8 + fg;
        int d0 = ks * 16 + fc * 2;
        float e00 = __ldg(emb + (d0 + 0) * K_CODES + n);
        float e01 = __ldg(emb + (d0 + 1) * K_CODES + n);
        float e10 = __ldg(emb + (d0 + 8) * K_CODES + n);
        float e11 = __ldg(emb + (d0 + 9) * K_CODES + n);
        sBH[i] = make_uint2(pack_bf2(e00, e01), pack_bf2(e10, e11));
        g_embT[n * D_DIM + d0]     = e00;
        g_embT[n * D_DIM + d0 + 1] = e01;
        g_embT[n * D_DIM + d0 + 8] = e10;
        g_embT[n * D_DIM + d0 + 9] = e11;
    }
    // ---- Prologue 2: exact code norms + global split-error maxima ----
    {
        const int k = tid;   // one code per thread (512 == BLOCK)
        float sn = 0.f, se = 0.f, sh = 0.f;
        #pragma unroll 8
        for (int d = 0; d < D_DIM; d++) {
            float v = emb[d * K_CODES + k];
            float h = __bfloat162float(__float2bfloat16(v));
            float r = v - h;
            sn = fmaf(v, v, sn);
            se = fmaf(r, r, se);
            sh = fmaf(h, h, sh);
        }
        snm[k] = sn;
        atomicMax(sSE2, __float_as_int(se));   // nonneg floats: int cmp == float cmp
        atomicMax(sSH2, __float_as_int(sh));
    }
    __syncthreads();

    const float S_e = sqrtf(__int_as_float(*sSE2)) * 1.0001f;
    const float S_h = sqrtf(__int_as_float(*sSH2)) * 1.0001f;

    double lacc = 0.0;

    for (int tile = blockIdx.x; tile < NTILES; tile += GRID) {
        const int rbase = tile * 128 + rg * 16 + g;

        // ---- A fragments (hi split only) + per-row norm / residual-norm ----
        uint32_t Ah[4][4];
        float xn0 = 0.f, xn1 = 0.f, rx0 = 0.f, rx1 = 0.f;
        {
            const float* xr0 = x + (size_t)rbase * D_DIM;
            const float* xr1 = xr0 + 8 * D_DIM;
            #pragma unroll
            for (int ks = 0; ks < 4; ks++) {
                #pragma unroll
                for (int p = 0; p < 2; p++) {
                    int col = 2 * c + 8 * p + 16 * ks;
                    float2 v0 = *(const float2*)(xr0 + col);
                    float2 v1 = *(const float2*)(xr1 + col);
                    xn0 = fmaf(v0.x, v0.x, fmaf(v0.y, v0.y, xn0));
                    xn1 = fmaf(v1.x, v1.x, fmaf(v1.y, v1.y, xn1));
                    float h0x = __bfloat162float(__float2bfloat16(v0.x));
                    float h0y = __bfloat162float(__float2bfloat16(v0.y));
                    float h1x = __bfloat162float(__float2bfloat16(v1.x));
                    float h1y = __bfloat162float(__float2bfloat16(v1.y));
                    float r0x = v0.x - h0x, r0y = v0.y - h0y;
                    float r1x = v1.x - h1x, r1y = v1.y - h1y;
                    rx0 = fmaf(r0x, r0x, fmaf(r0y, r0y, rx0));
                    rx1 = fmaf(r1x, r1x, fmaf(r1y, r1y, rx1));
                    Ah[ks][2 * p]     = pack_bf2(v0.x, v0.y);
                    Ah[ks][2 * p + 1] = pack_bf2(v1.x, v1.y);
                }
            }
        }
        // quad reduce norms
        #pragma unroll
        for (int off = 1; off <= 2; off <<= 1) {
            xn0 += __shfl_xor_sync(0xffffffffu, xn0, off);
            xn1 += __shfl_xor_sync(0xffffffffu, xn1, off);
            rx0 += __shfl_xor_sync(0xffffffffu, rx0, off);
            rx1 += __shfl_xor_sync(0xffffffffu, rx1, off);
        }
        if (c == 0 && nh == 0) {
            const int r = rg * 16 + g;
            sxn[r] = xn0;  sxn[r + 8] = xn1;
            srx[r] = rx0;  srx[r + 8] = rx1;
        }

        // ---- Stage A: estimate distances (hi-hi term only), store fp16 ----
        float m0 = FLT_MAX, m1 = FLT_MAX;
        const int ntbeg = nh * 32;
        #pragma unroll 1
        for (int nt0 = ntbeg; nt0 < ntbeg + 32; nt0 += 4) {
            float acc[4][4];
            #pragma unroll
            for (int u = 0; u < 4; u++)
                #pragma unroll
                for (int r = 0; r < 4; r++) acc[u][r] = 0.f;

            #pragma unroll
            for (int ks = 0; ks < 4; ks++)
                #pragma unroll
                for (int u = 0; u < 4; u++) {
                    uint2 b = sBH[((nt0 + u) * 4 + ks) * 32 + lane];
                    MMA(acc[u], Ah[ks], b.x, b.y);
                }

            #pragma unroll
            for (int u = 0; u < 4; u++) {
                const int kb = (nt0 + u) * 8 + 2 * c;
                float2 s2 = *(const float2*)(snm + kb);
                float e00 = fmaf(-2.f, acc[u][0], s2.x);
                float e01 = fmaf(-2.f, acc[u][1], s2.y);
                float e10 = fmaf(-2.f, acc[u][2], s2.x);
                float e11 = fmaf(-2.f, acc[u][3], s2.y);
                m0 = fminf(m0, fminf(e00, e01));
                m1 = fminf(m1, fminf(e10, e11));
                const int r0 = rg * 16 + g;
                *(__half2*)(sEst + r0 * EST_STRIDE + kb)       = __floats2half2_rn(e00, e01);
                *(__half2*)(sEst + (r0 + 8) * EST_STRIDE + kb) = __floats2half2_rn(e10, e11);
            }
        }
        #pragma unroll
        for (int off = 1; off <= 2; off <<= 1) {
            m0 = fminf(m0, __shfl_xor_sync(0xffffffffu, m0, off));
            m1 = fminf(m1, __shfl_xor_sync(0xffffffffu, m1, off));
        }
        if (c == 0) {
            const int r = rg * 16 + g;
            smin[nh * 128 + r]     = m0;
            smin[nh * 128 + r + 8] = m1;
        }
        __syncthreads();

        // ---- per-row candidate threshold (rigorous C-S bound + slack) ----
        if (tid < 128) {
            float minest = fminf(smin[tid], smin[128 + tid]);
            float bnd = 2.f * (sqrtf(sxn[tid]) * S_e + sqrtf(srx[tid]) * S_h);
            sthr[tid] = minest + 2.10f * bnd + 0.35f;
        }
        __syncthreads();

        // ---- Stage B: scan estimates, exact-rescore candidates ----
        #pragma unroll 1
        for (int rr = 0; rr < 8; rr++) {
            const int row  = w * 8 + rr;
            const int grow = tile * 128 + row;
            float2 xv = ((const float2*)(x + (size_t)grow * D_DIM))[lane];
            const float thr = sthr[row];
            float best = FLT_MAX;
            int   bk   = 0;
            #pragma unroll 1
            for (int j = 0; j < 8; j++) {
                __half2 h2 = *(const __half2*)(sEst + row * EST_STRIDE + 64 * j + 2 * lane);
                float2 ef = __half22float2(h2);
                unsigned blo = __ballot_sync(0xffffffffu, ef.x <= thr);
                unsigned bhi = __ballot_sync(0xffffffffu, ef.y <= thr);
                unsigned msk = blo | bhi;
                while (msk) {
                    int l = __ffs(msk) - 1;
                    msk &= msk - 1;
                    #pragma unroll
                    for (int h = 0; h < 2; h++) {
                        if (((h ? bhi : blo) >> l) & 1) {
                            const int k = 64 * j + 2 * l + h;
                            float2 ev = ((const float2*)(g_embT + k * D_DIM))[lane];
                            float dx = xv.x - ev.x, dy = xv.y - ev.y;
                            float p = fmaf(dx, dx, dy * dy);
                            #pragma unroll
                            for (int off = 16; off > 0; off >>= 1)
                                p += __shfl_xor_sync(0xffffffffu, p, off);
                            if (p < best) { best = p; bk = k; }   // ascending k => first min wins
                        }
                    }
                }
            }
            if (lane == 0) { sbk[row] = bk; lacc += (double)best; }
        }
        __syncthreads();

        // ---- output: exact fp32 codebook rows (4 threads per row) ----
        {
            const int r = tid >> 2;
            const int q = tid & 3;
            const int k = sbk[r];
            const float4* src = (const float4*)(g_embT + k * D_DIM) + q * 4;
            float4* dst = (float4*)(out + (size_t)(tile * 128 + r) * D_DIM) + q * 4;
            dst[0] = src[0]; dst[1] = src[1]; dst[2] = src[2]; dst[3] = src[3];
        }
        __syncthreads();   // sEst/sbk reused next tile
    }

    // ---- loss: warp reduce -> CTA partial -> last block finalizes ----
    #pragma unroll
    for (int off = 16; off > 0; off >>= 1)
        lacc += __shfl_down_sync(0xffffffffu, lacc, off);
    if (lane == 0) sls[w] = lacc;
    __syncthreads();
    if (tid == 0) {
        double t = 0.0;
        #pragma unroll
        for (int i = 0; i < 16; i++) t += sls[i];
        g_partial[blockIdx.x] = t;
        __threadfence();
        unsigned n = atomicAdd(&g_cnt, 1u);
        if (n == GRID - 1) {
            __threadfence();
            double tot = 0.0;
            for (int i = 0; i < GRID; i++) tot += g_partial[i];
            if (write_loss)
                out[(size_t)NROWS * D_DIM] =
                    (float)(tot * (1.25 / ((double)NROWS * (double)D_DIM)));
            g_cnt = 0;   // reset for next graph replay
        }
    }
}

extern "C" void kernel_launch(void* const* d_in, const int* in_sizes, int n_in,
                              void* d_out, int out_size)
{
    const float* x   = (const float*)d_in[0];
    const float* emb = (const float*)d_in[1];
    float* out = (float*)d_out;

    const int write_loss = (out_size > NROWS * D_DIM) ? 1 : 0;

    static int configured = 0;
    if (!configured) {
        cudaFuncSetAttribute(vq_2stage, cudaFuncAttributeMaxDynamicSharedMemorySize, SMEM_TOTAL);
        configured = 1;
    }
    vq_2stage<<<GRID, BLOCK, SMEM_TOTAL>>>(x, emb, out, write_loss);
}